// round 11
// baseline (speedup 1.0000x reference)
#include <cuda_runtime.h>

// ---------------------------------------------------------------------------
// QuantumHybridHead, Heisenberg-picture reduction (see R2 derivation).
// z0 = c0 <Z1 Z2 Z3> + s0 <X0 Y1 Z2 Z3>
// z1 = c1 <Z0 Z1>    + s1 <Z0 Y1 X2>
// z2 = c2 <Z0 Z1 Z2> + s2 <Z0 Z1 Y2 X3>
// z3 = c3 <Z0Z1Z2Z3> - s3 <Y0 Y1 Z2 Y3>
// Product state => per-wire affine expectations E(w) = p + q cos w + r sin w.
// R10: constants stored PRE-DUPLICATED in smem (each value twice, adjacent)
// so packed f32x2 operands load directly via 16x LDS.128 — removes the 32
// pk2 broadcast-MOVs per thread from R9. Everything else = R9 best config.
// ---------------------------------------------------------------------------

typedef unsigned long long ull;

struct Cpx { float re, im; };

__device__ __forceinline__ Cpx cmul(Cpx a, Cpx b) {
    return { a.re * b.re - a.im * b.im, a.re * b.im + a.im * b.re };
}
__device__ __forceinline__ Cpx cconjmul(Cpx a, Cpx b) {  // conj(a)*b
    return { a.re * b.re + a.im * b.im, a.re * b.im - a.im * b.re };
}

// ---- packed f32x2 helpers (sm_103a) ----
__device__ __forceinline__ ull pk2(float a, float b) {
    ull r; asm("mov.b64 %0, {%1, %2};" : "=l"(r) : "f"(a), "f"(b)); return r;
}
__device__ __forceinline__ void upk2(ull v, float& a, float& b) {
    asm("mov.b64 {%0, %1}, %2;" : "=f"(a), "=f"(b) : "l"(v));
}
__device__ __forceinline__ ull f2fma(ull a, ull b, ull c) {
    ull r; asm("fma.rn.f32x2 %0, %1, %2, %3;" : "=l"(r) : "l"(a), "l"(b), "l"(c));
    return r;
}
__device__ __forceinline__ ull f2mul(ull a, ull b) {
    ull r; asm("mul.rn.f32x2 %0, %1, %2;" : "=l"(r) : "l"(a), "l"(b)); return r;
}

// G = Rz(th[2]) * Ry(th[1]) * Rx(th[0])
__device__ __forceinline__ void gateG(const float* __restrict__ th,
                                      Cpx& g00, Cpx& g01, Cpx& g10, Cpx& g11) {
    float cx, sx, cy, sy, cz, sz;
    __sincosf(0.5f * th[0], &sx, &cx);
    __sincosf(0.5f * th[1], &sy, &cy);
    __sincosf(0.5f * th[2], &sz, &cz);
    Cpx m00 = { cy * cx,  sy * sx };
    Cpx m01 = { -sy * cx, -cy * sx };
    Cpx m10 = { sy * cx,  -cy * sx };
    Cpx m11 = { cy * cx,  -sy * sx };
    Cpx e0 = { cz, -sz };
    Cpx e1 = { cz,  sz };
    g00 = cmul(e0, m00); g01 = cmul(e0, m01);
    g10 = cmul(e1, m10); g11 = cmul(e1, m11);
}

// tmp[0..8] = pZ qZ rZ pX qX rX pY qY rY
__device__ __forceinline__ void wireConsts(Cpx g00, Cpx g01, Cpx g10, Cpx g11,
                                           bool k_minus_i, float* tmp) {
    float n00 = g00.re * g00.re + g00.im * g00.im;
    float n01 = g01.re * g01.re + g01.im * g01.im;
    float n10 = g10.re * g10.re + g10.im * g10.im;
    float n11 = g11.re * g11.re + g11.im * g11.im;
    float AZ = n00 - n10, BZ = n01 - n11;
    Cpx a01 = cconjmul(g00, g01);
    Cpx b01 = cconjmul(g10, g11);
    Cpx CZ = { a01.re - b01.re, a01.im - b01.im };
    Cpx c00 = cconjmul(g00, g10);
    Cpx c01 = cconjmul(g01, g11);
    float AX = 2.0f * c00.re, BX = 2.0f * c01.re;
    Cpx t1 = cconjmul(g00, g11);
    Cpx t2 = cconjmul(g10, g01);
    Cpx CX = { t1.re + t2.re, t1.im + t2.im };
    float AY = 2.0f * c00.im, BY = 2.0f * c01.im;
    Cpx D = { t2.re - t1.re, t2.im - t1.im };
    Cpx CY = { -D.im, D.re };                   // i*D
    tmp[0] = 0.5f * (AZ + BZ); tmp[1] = 0.5f * (AZ - BZ);
    tmp[2] = k_minus_i ? CZ.im : CZ.re;
    tmp[3] = 0.5f * (AX + BX); tmp[4] = 0.5f * (AX - BX);
    tmp[5] = k_minus_i ? CX.im : CX.re;
    tmp[6] = 0.5f * (AY + BY); tmp[7] = 0.5f * (AY - BY);
    tmp[8] = k_minus_i ? CY.im : CY.re;
}

// Duplicated-pair smem layout: logical const k lives at sc2[2k] and sc2[2k+1],
// so ((const ull*)sc2)[k] is the packed (c, c) f32x2 operand directly.
// Logical layout (same as R9):
//  [0..8]   wire0: Z(p,q,r) X(p,q,r) Y(p,q,r)
//  [9..14]  wire1: Z(p,q,r) Y(p,q,r)
//  [15..23] wire3: Z(p,q,r) X(p,q,r) Y(p,q,r)
//  [24..31] A0 B0 A1 B1 A2a A2b A3 B3n   (B3n stored NEGATED)
__device__ __forceinline__ void wr2(float* sc2, int k, float v) {
    sc2[2 * k] = v; sc2[2 * k + 1] = v;
}

__device__ __forceinline__ void precompute_block(const float* __restrict__ theta,
                                                 float* __restrict__ sc2, int t) {
    if (t < 4) {
        if (t < 3) {
            int q = (t == 2) ? 3 : t;
            Cpx g00, g01, g10, g11;
            gateG(theta + 3 * q, g00, g01, g10, g11);
            float tmp[9];
            wireConsts(g00, g01, g10, g11, t != 1, tmp);
            if (t == 0) {
                #pragma unroll
                for (int k = 0; k < 9; k++) wr2(sc2, k, tmp[k]);
            } else if (t == 1) {
                wr2(sc2, 9,  tmp[0]); wr2(sc2, 10, tmp[1]); wr2(sc2, 11, tmp[2]);
                wr2(sc2, 12, tmp[6]); wr2(sc2, 13, tmp[7]); wr2(sc2, 14, tmp[8]);
            } else {
                #pragma unroll
                for (int k = 0; k < 9; k++) wr2(sc2, 15 + k, tmp[k]);
            }
        } else {
            Cpx g00, g01, g10, g11;
            gateG(theta + 6, g00, g01, g10, g11);
            // u2 = G2 |0> = (g00, g10)
            float z2c = (g00.re * g00.re + g00.im * g00.im)
                      - (g10.re * g10.re + g10.im * g10.im);
            Cpx cr = cconjmul(g00, g10);
            float x2c = 2.0f * cr.re;
            float y2c = 2.0f * cr.im;
            float cw[4], sw[4];
            #pragma unroll
            for (int q = 0; q < 4; q++) __sincosf(theta[12 + q], &sw[q], &cw[q]);
            wr2(sc2, 24, cw[0] * z2c);   // A0
            wr2(sc2, 25, sw[0] * z2c);   // B0
            wr2(sc2, 26, cw[1]);         // A1
            wr2(sc2, 27, sw[1] * x2c);   // B1
            wr2(sc2, 28, cw[2] * z2c);   // A2a
            wr2(sc2, 29, sw[2] * y2c);   // A2b
            wr2(sc2, 30, cw[3] * z2c);   // A3
            wr2(sc2, 31, -sw[3] * z2c);  // B3n (ow = A3*z01*z3 + B3n*y0*y1*y3)
        }
    }
}

// Packed two-sample evaluation. Cp[k] = (C[k], C[k]).
__device__ __forceinline__ void sample_pair(const ull* __restrict__ Cp,
                                            float4 wa, float4 wb,
                                            float4& oa, float4& ob) {
    float c0a, s0a, c1a, s1a, c3a, s3a;
    float c0b, s0b, c1b, s1b, c3b, s3b;
    __sincosf(wa.x, &s0a, &c0a);  __sincosf(wb.x, &s0b, &c0b);
    __sincosf(wa.y, &s1a, &c1a);  __sincosf(wb.y, &s1b, &c1b);
    __sincosf(wa.w, &s3a, &c3a);  __sincosf(wb.w, &s3b, &c3b);
    ull cw0 = pk2(c0a, c0b), sw0 = pk2(s0a, s0b);
    ull cw1 = pk2(c1a, c1b), sw1 = pk2(s1a, s1b);
    ull cw3 = pk2(c3a, c3b), sw3 = pk2(s3a, s3b);

    ull z0 = f2fma(Cp[1],  cw0, f2fma(Cp[2],  sw0, Cp[0]));
    ull x0 = f2fma(Cp[4],  cw0, f2fma(Cp[5],  sw0, Cp[3]));
    ull y0 = f2fma(Cp[7],  cw0, f2fma(Cp[8],  sw0, Cp[6]));
    ull z1 = f2fma(Cp[10], cw1, f2fma(Cp[11], sw1, Cp[9]));
    ull y1 = f2fma(Cp[13], cw1, f2fma(Cp[14], sw1, Cp[12]));
    ull z3 = f2fma(Cp[16], cw3, f2fma(Cp[17], sw3, Cp[15]));
    ull x3 = f2fma(Cp[19], cw3, f2fma(Cp[20], sw3, Cp[18]));
    ull y3 = f2fma(Cp[22], cw3, f2fma(Cp[23], sw3, Cp[21]));

    ull z01 = f2mul(z0, z1);
    ull ox = f2mul(z3, f2fma(Cp[25], f2mul(x0, y1), f2mul(Cp[24], z1)));
    ull oy = f2mul(z0, f2fma(Cp[27], y1, f2mul(Cp[26], z1)));
    ull oz = f2mul(z01, f2fma(Cp[29], x3, Cp[28]));
    ull ow = f2fma(Cp[30], f2mul(z01, z3),
                   f2mul(Cp[31], f2mul(f2mul(y0, y1), y3)));

    upk2(ox, oa.x, ob.x);
    upk2(oy, oa.y, ob.y);
    upk2(oz, oa.z, ob.z);
    upk2(ow, oa.w, ob.w);
}

static constexpr int SPT  = 4;     // samples per thread (2 packed pairs)
static constexpr int NTHR = 128;   // threads per block

template <bool CHECKED>
__global__ void __launch_bounds__(NTHR)
qsim_kernel(const float4* __restrict__ inp, const float* __restrict__ theta,
            float4* __restrict__ out, int n, int nthreads) {
    __shared__ __align__(16) float sc2[64];   // duplicated-pair constants
    int t = threadIdx.x;
    int tid = blockIdx.x * NTHR + t;

    // ---- Front-batch all SPT input loads (independent of the constants);
    //      the precompute chain + barrier hide under this latency. ----
    float4 w[SPT];
    #pragma unroll
    for (int k = 0; k < SPT; k++) {
        int i = tid + k * nthreads;
        if (!CHECKED || i < n) w[k] = __ldg(&inp[i]);
    }

    // ---- Block-level constant precompute (threads 0..3) ----
    precompute_block(theta, sc2, t);
    __syncthreads();

    // Packed constants loaded directly: 16x LDS.128 (two f32x2 each),
    // broadcast across the warp, zero packing instructions.
    ull Cp[32];
    #pragma unroll
    for (int k = 0; k < 16; k++) {
        ulonglong2 v = reinterpret_cast<const ulonglong2*>(sc2)[k];
        Cp[2 * k + 0] = v.x;
        Cp[2 * k + 1] = v.y;
    }

    // ---- Two packed pairs: (0,1) and (2,3) ----
    #pragma unroll
    for (int p = 0; p < SPT / 2; p++) {
        int ia = tid + (2 * p + 0) * nthreads;
        int ib = tid + (2 * p + 1) * nthreads;
        if (!CHECKED || ib < n) {
            float4 oa, ob;
            sample_pair(Cp, w[2 * p], w[2 * p + 1], oa, ob);
            out[ia] = oa;
            out[ib] = ob;
        } else if (ia < n) {
            // tail: single sample, duplicate into a pair
            float4 oa, ob;
            sample_pair(Cp, w[2 * p], w[2 * p], oa, ob);
            out[ia] = oa;
        }
    }
}

extern "C" void kernel_launch(void* const* d_in, const int* in_sizes, int n_in,
                              void* d_out, int out_size) {
    const float* inputs = (const float*)d_in[0];   // [B, 4] float32
    const float* theta  = (const float*)d_in[1];   // [16] float32
    float* out = (float*)d_out;                    // [B, 4, 1] float32

    int n = in_sizes[0] / 4;                 // samples
    int per = (n + SPT - 1) / SPT;           // samples per lane-index slot
    int blocks = (per + NTHR - 1) / NTHR;    // 1024 for B = 2^19
    int nthreads = blocks * NTHR;

    if (nthreads * SPT == n) {
        // Exact division (B = 2^19 hits this): no bounds checks on hot path.
        qsim_kernel<false><<<blocks, NTHR>>>((const float4*)inputs, theta,
                                             (float4*)out, n, nthreads);
    } else {
        qsim_kernel<true><<<blocks, NTHR>>>((const float4*)inputs, theta,
                                            (float4*)out, n, nthreads);
    }
}

// round 12
// speedup vs baseline: 1.3495x; 1.3495x over previous
#include <cuda_runtime.h>

// ---------------------------------------------------------------------------
// QuantumHybridHead, Heisenberg-picture reduction (see R2 derivation).
// z0 = c0 <Z1 Z2 Z3> + s0 <X0 Y1 Z2 Z3>
// z1 = c1 <Z0 Z1>    + s1 <Z0 Y1 X2>
// z2 = c2 <Z0 Z1 Z2> + s2 <Z0 Z1 Y2 X3>
// z3 = c3 <Z0Z1Z2Z3> - s3 <Y0 Y1 Z2 Y3>
// Product state => per-wire affine expectations E(w) = p + q cos w + r sin w.
// FINAL (= R9, best measured: kernel 6.53us): packed f32x2 arithmetic
// (fma.rn.f32x2 / mul.rn.f32x2) processes two samples per instruction in the
// FMA-heavy sample math. Front-batched LDG.128 (MLP=4) hide the block-level
// constant precompute; plain STG; exact-division unchecked hot path.
// ---------------------------------------------------------------------------

typedef unsigned long long ull;

struct Cpx { float re, im; };

__device__ __forceinline__ Cpx cmul(Cpx a, Cpx b) {
    return { a.re * b.re - a.im * b.im, a.re * b.im + a.im * b.re };
}
__device__ __forceinline__ Cpx cconjmul(Cpx a, Cpx b) {  // conj(a)*b
    return { a.re * b.re + a.im * b.im, a.re * b.im - a.im * b.re };
}

// ---- packed f32x2 helpers (sm_103a) ----
__device__ __forceinline__ ull pk2(float a, float b) {
    ull r; asm("mov.b64 %0, {%1, %2};" : "=l"(r) : "f"(a), "f"(b)); return r;
}
__device__ __forceinline__ void upk2(ull v, float& a, float& b) {
    asm("mov.b64 {%0, %1}, %2;" : "=f"(a), "=f"(b) : "l"(v));
}
__device__ __forceinline__ ull f2fma(ull a, ull b, ull c) {
    ull r; asm("fma.rn.f32x2 %0, %1, %2, %3;" : "=l"(r) : "l"(a), "l"(b), "l"(c));
    return r;
}
__device__ __forceinline__ ull f2mul(ull a, ull b) {
    ull r; asm("mul.rn.f32x2 %0, %1, %2;" : "=l"(r) : "l"(a), "l"(b)); return r;
}

// G = Rz(th[2]) * Ry(th[1]) * Rx(th[0])
__device__ __forceinline__ void gateG(const float* __restrict__ th,
                                      Cpx& g00, Cpx& g01, Cpx& g10, Cpx& g11) {
    float cx, sx, cy, sy, cz, sz;
    __sincosf(0.5f * th[0], &sx, &cx);
    __sincosf(0.5f * th[1], &sy, &cy);
    __sincosf(0.5f * th[2], &sz, &cz);
    Cpx m00 = { cy * cx,  sy * sx };
    Cpx m01 = { -sy * cx, -cy * sx };
    Cpx m10 = { sy * cx,  -cy * sx };
    Cpx m11 = { cy * cx,  -sy * sx };
    Cpx e0 = { cz, -sz };
    Cpx e1 = { cz,  sz };
    g00 = cmul(e0, m00); g01 = cmul(e0, m01);
    g10 = cmul(e1, m10); g11 = cmul(e1, m11);
}

// tmp[0..8] = pZ qZ rZ pX qX rX pY qY rY
__device__ __forceinline__ void wireConsts(Cpx g00, Cpx g01, Cpx g10, Cpx g11,
                                           bool k_minus_i, float* tmp) {
    float n00 = g00.re * g00.re + g00.im * g00.im;
    float n01 = g01.re * g01.re + g01.im * g01.im;
    float n10 = g10.re * g10.re + g10.im * g10.im;
    float n11 = g11.re * g11.re + g11.im * g11.im;
    float AZ = n00 - n10, BZ = n01 - n11;
    Cpx a01 = cconjmul(g00, g01);
    Cpx b01 = cconjmul(g10, g11);
    Cpx CZ = { a01.re - b01.re, a01.im - b01.im };
    Cpx c00 = cconjmul(g00, g10);
    Cpx c01 = cconjmul(g01, g11);
    float AX = 2.0f * c00.re, BX = 2.0f * c01.re;
    Cpx t1 = cconjmul(g00, g11);
    Cpx t2 = cconjmul(g10, g01);
    Cpx CX = { t1.re + t2.re, t1.im + t2.im };
    float AY = 2.0f * c00.im, BY = 2.0f * c01.im;
    Cpx D = { t2.re - t1.re, t2.im - t1.im };
    Cpx CY = { -D.im, D.re };                   // i*D
    tmp[0] = 0.5f * (AZ + BZ); tmp[1] = 0.5f * (AZ - BZ);
    tmp[2] = k_minus_i ? CZ.im : CZ.re;
    tmp[3] = 0.5f * (AX + BX); tmp[4] = 0.5f * (AX - BX);
    tmp[5] = k_minus_i ? CX.im : CX.re;
    tmp[6] = 0.5f * (AY + BY); tmp[7] = 0.5f * (AY - BY);
    tmp[8] = k_minus_i ? CY.im : CY.re;
}

// Const layout (32 floats, 16B-aligned):
//  [0..8]   wire0: Z(p,q,r) X(p,q,r) Y(p,q,r)
//  [9..14]  wire1: Z(p,q,r) Y(p,q,r)
//  [15..23] wire3: Z(p,q,r) X(p,q,r) Y(p,q,r)
//  [24..31] A0 B0 A1 B1 A2a A2b A3 B3n   (B3n stored NEGATED)
__device__ __forceinline__ void precompute_block(const float* __restrict__ theta,
                                                 float* __restrict__ sc, int t) {
    if (t < 4) {
        if (t < 3) {
            int q = (t == 2) ? 3 : t;
            Cpx g00, g01, g10, g11;
            gateG(theta + 3 * q, g00, g01, g10, g11);
            float tmp[9];
            wireConsts(g00, g01, g10, g11, t != 1, tmp);
            if (t == 0) {
                #pragma unroll
                for (int k = 0; k < 9; k++) sc[k] = tmp[k];
            } else if (t == 1) {
                sc[9]  = tmp[0]; sc[10] = tmp[1]; sc[11] = tmp[2];
                sc[12] = tmp[6]; sc[13] = tmp[7]; sc[14] = tmp[8];
            } else {
                #pragma unroll
                for (int k = 0; k < 9; k++) sc[15 + k] = tmp[k];
            }
        } else {
            Cpx g00, g01, g10, g11;
            gateG(theta + 6, g00, g01, g10, g11);
            // u2 = G2 |0> = (g00, g10)
            float z2c = (g00.re * g00.re + g00.im * g00.im)
                      - (g10.re * g10.re + g10.im * g10.im);
            Cpx cr = cconjmul(g00, g10);
            float x2c = 2.0f * cr.re;
            float y2c = 2.0f * cr.im;
            float cw[4], sw[4];
            #pragma unroll
            for (int q = 0; q < 4; q++) __sincosf(theta[12 + q], &sw[q], &cw[q]);
            sc[24] = cw[0] * z2c;   // A0
            sc[25] = sw[0] * z2c;   // B0
            sc[26] = cw[1];         // A1
            sc[27] = sw[1] * x2c;   // B1
            sc[28] = cw[2] * z2c;   // A2a
            sc[29] = sw[2] * y2c;   // A2b
            sc[30] = cw[3] * z2c;   // A3
            sc[31] = -sw[3] * z2c;  // B3n (negated: ow = A3*z01*z3 + B3n*y0*y1*y3)
        }
    }
}

// Packed two-sample evaluation. Cp[k] = (C[k], C[k]).
__device__ __forceinline__ void sample_pair(const ull* __restrict__ Cp,
                                            float4 wa, float4 wb,
                                            float4& oa, float4& ob) {
    float c0a, s0a, c1a, s1a, c3a, s3a;
    float c0b, s0b, c1b, s1b, c3b, s3b;
    __sincosf(wa.x, &s0a, &c0a);  __sincosf(wb.x, &s0b, &c0b);
    __sincosf(wa.y, &s1a, &c1a);  __sincosf(wb.y, &s1b, &c1b);
    __sincosf(wa.w, &s3a, &c3a);  __sincosf(wb.w, &s3b, &c3b);
    ull cw0 = pk2(c0a, c0b), sw0 = pk2(s0a, s0b);
    ull cw1 = pk2(c1a, c1b), sw1 = pk2(s1a, s1b);
    ull cw3 = pk2(c3a, c3b), sw3 = pk2(s3a, s3b);

    ull z0 = f2fma(Cp[1],  cw0, f2fma(Cp[2],  sw0, Cp[0]));
    ull x0 = f2fma(Cp[4],  cw0, f2fma(Cp[5],  sw0, Cp[3]));
    ull y0 = f2fma(Cp[7],  cw0, f2fma(Cp[8],  sw0, Cp[6]));
    ull z1 = f2fma(Cp[10], cw1, f2fma(Cp[11], sw1, Cp[9]));
    ull y1 = f2fma(Cp[13], cw1, f2fma(Cp[14], sw1, Cp[12]));
    ull z3 = f2fma(Cp[16], cw3, f2fma(Cp[17], sw3, Cp[15]));
    ull x3 = f2fma(Cp[19], cw3, f2fma(Cp[20], sw3, Cp[18]));
    ull y3 = f2fma(Cp[22], cw3, f2fma(Cp[23], sw3, Cp[21]));

    ull z01 = f2mul(z0, z1);
    ull ox = f2mul(z3, f2fma(Cp[25], f2mul(x0, y1), f2mul(Cp[24], z1)));
    ull oy = f2mul(z0, f2fma(Cp[27], y1, f2mul(Cp[26], z1)));
    ull oz = f2mul(z01, f2fma(Cp[29], x3, Cp[28]));
    ull ow = f2fma(Cp[30], f2mul(z01, z3),
                   f2mul(Cp[31], f2mul(f2mul(y0, y1), y3)));

    upk2(ox, oa.x, ob.x);
    upk2(oy, oa.y, ob.y);
    upk2(oz, oa.z, ob.z);
    upk2(ow, oa.w, ob.w);
}

static constexpr int SPT  = 4;     // samples per thread (2 packed pairs)
static constexpr int NTHR = 128;   // threads per block

template <bool CHECKED>
__global__ void __launch_bounds__(NTHR)
qsim_kernel(const float4* __restrict__ inp, const float* __restrict__ theta,
            float4* __restrict__ out, int n, int nthreads) {
    __shared__ __align__(16) float sc[32];
    int t = threadIdx.x;
    int tid = blockIdx.x * NTHR + t;

    // ---- Front-batch all SPT input loads (independent of the constants);
    //      the precompute chain + barrier hide under this latency. ----
    float4 w[SPT];
    #pragma unroll
    for (int k = 0; k < SPT; k++) {
        int i = tid + k * nthreads;
        if (!CHECKED || i < n) w[k] = __ldg(&inp[i]);
    }

    // ---- Block-level constant precompute (threads 0..3) ----
    precompute_block(theta, sc, t);
    __syncthreads();

    // Read constants via 8x LDS.128, then broadcast-pack each as (c, c).
    ull Cp[32];
    #pragma unroll
    for (int k = 0; k < 8; k++) {
        float4 v = reinterpret_cast<const float4*>(sc)[k];
        Cp[4 * k + 0] = pk2(v.x, v.x);
        Cp[4 * k + 1] = pk2(v.y, v.y);
        Cp[4 * k + 2] = pk2(v.z, v.z);
        Cp[4 * k + 3] = pk2(v.w, v.w);
    }

    // ---- Two packed pairs: (0,1) and (2,3) ----
    #pragma unroll
    for (int p = 0; p < SPT / 2; p++) {
        int ia = tid + (2 * p + 0) * nthreads;
        int ib = tid + (2 * p + 1) * nthreads;
        if (!CHECKED || ib < n) {
            float4 oa, ob;
            sample_pair(Cp, w[2 * p], w[2 * p + 1], oa, ob);
            out[ia] = oa;
            out[ib] = ob;
        } else if (ia < n) {
            // tail: single sample, duplicate into a pair
            float4 oa, ob;
            sample_pair(Cp, w[2 * p], w[2 * p], oa, ob);
            out[ia] = oa;
        }
    }
}

extern "C" void kernel_launch(void* const* d_in, const int* in_sizes, int n_in,
                              void* d_out, int out_size) {
    const float* inputs = (const float*)d_in[0];   // [B, 4] float32
    const float* theta  = (const float*)d_in[1];   // [16] float32
    float* out = (float*)d_out;                    // [B, 4, 1] float32

    int n = in_sizes[0] / 4;                 // samples
    int per = (n + SPT - 1) / SPT;           // samples per lane-index slot
    int blocks = (per + NTHR - 1) / NTHR;    // 1024 for B = 2^19
    int nthreads = blocks * NTHR;

    if (nthreads * SPT == n) {
        // Exact division (B = 2^19 hits this): no bounds checks on hot path.
        qsim_kernel<false><<<blocks, NTHR>>>((const float4*)inputs, theta,
                                             (float4*)out, n, nthreads);
    } else {
        qsim_kernel<true><<<blocks, NTHR>>>((const float4*)inputs, theta,
                                            (float4*)out, n, nthreads);
    }
}